// round 1
// baseline (speedup 1.0000x reference)
#include <cuda_runtime.h>
#include <cstdint>
#include <cstddef>

// ============================================================================
// AttentionOperation: S=QtK -> BN(head) -> softmax -> attn@V -> BN(chan) -> gelu
// N=8 H=8 D=C=64 L=M=1024.
// Strategy: BN1 shift cancels in softmax; only a_h = gamma*rstd matters.
//   K1: GEMM1 (fp32, packed f32x2 FMA) -> S scratch + per-head sum/sumsq +
//       per-row raw max/min (ordered-uint atomics).
//   K2: finalize per-head scale (in log2 domain).
//   K3: GEMM2 fused softmax: e=exp2(aL2E*s - zmax) on the fly, U=sum(e*v),
//       rowsum alongside, divide in epilogue, write rv into d_out (same layout),
//       accumulate per-channel sum/sumsq.
//   K4: finalize per-channel scale/bias.  K5: BN2 + exact gelu in place.
// ============================================================================

typedef unsigned long long ull;

__device__ __forceinline__ ull f2u(float x, float y) {
    ull u; asm("mov.b64 %0,{%1,%2};" : "=l"(u) : "f"(x), "f"(y)); return u;
}
__device__ __forceinline__ float2 u2f(ull u) {
    float2 f; asm("mov.b64 {%0,%1},%2;" : "=f"(f.x), "=f"(f.y) : "l"(u)); return f;
}
__device__ __forceinline__ ull fma2(ull a, ull b, ull c) {
    ull d; asm("fma.rn.f32x2 %0,%1,%2,%3;" : "=l"(d) : "l"(a), "l"(b), "l"(c)); return d;
}

// Monotonic float<->uint encoding for atomicMax/Min over signed floats
__device__ __forceinline__ unsigned encf(float f) {
    unsigned u = __float_as_uint(f);
    return (u & 0x80000000u) ? ~u : (u | 0x80000000u);
}
__device__ __forceinline__ float decf(unsigned e) {
    return __uint_as_float((e & 0x80000000u) ? (e & 0x7fffffffu) : ~e);
}

// ---------------- scratch (device globals; no runtime allocation) -----------
__device__ float    g_S[67108864];   // 256 MB: S[bh][l][m]
__device__ unsigned g_rmax[65536];   // per-row raw max (encoded)
__device__ unsigned g_rmin[65536];   // per-row raw min (encoded)
__device__ float    g_hsum[8], g_hsq[8];
__device__ float    g_aL2E[8];       // gamma*rstd*log2(e) per head
__device__ float    g_vsum[512], g_vsq[512];
__device__ float    g_vscale[512], g_vbias[512];

// ---------------- K0: init accumulators (graph-replay deterministic) --------
__global__ void k_init() {
    int i = blockIdx.x * blockDim.x + threadIdx.x;   // 65536 threads
    g_rmax[i] = 0u;
    g_rmin[i] = 0xFFFFFFFFu;
    if (i < 512) { g_vsum[i] = 0.f; g_vsq[i] = 0.f; }
    if (i < 8)   { g_hsum[i] = 0.f; g_hsq[i] = 0.f; }
}

// ---------------- K1: GEMM1  S[l,m] = sum_d q[d,l]*k[d,m] -------------------
// grid (8 m-tiles, 8 l-tiles, 64 bh), 256 threads, tile 128x128, K-chunk 16.
// Thread (tx,ty): l = ty*8+i (i<8), m = tx*2 + 32*p (+0/+1) (p<4) -> 8x8 outs.
__global__ void __launch_bounds__(256) k_gemm1(const float* __restrict__ q,
                                               const float* __restrict__ kk) {
    const int bh = blockIdx.z;
    const int l0 = blockIdx.y << 7;
    const int m0 = blockIdx.x << 7;
    __shared__ float Qs[16][128];
    __shared__ float Ks[16][128];
    const int tid = threadIdx.x;
    const int tx = tid & 15, ty = tid >> 4;
    const float* qb = q  + (size_t)bh * 65536 + l0;
    const float* kb = kk + (size_t)bh * 65536 + m0;

    ull acc[8][4];
#pragma unroll
    for (int i = 0; i < 8; i++)
#pragma unroll
        for (int p = 0; p < 4; p++) acc[i][p] = 0ull;

    for (int d0 = 0; d0 < 64; d0 += 16) {
#pragma unroll
        for (int j = 0; j < 2; j++) {
            int f = tid + (j << 8);
            int dr = f >> 5, c4 = (f & 31) << 2;
            *(float4*)&Qs[dr][c4] = *(const float4*)&qb[(size_t)(d0 + dr) * 1024 + c4];
            *(float4*)&Ks[dr][c4] = *(const float4*)&kb[(size_t)(d0 + dr) * 1024 + c4];
        }
        __syncthreads();
#pragma unroll
        for (int kq = 0; kq < 16; kq++) {
            ull a2[8], b2[4];
#pragma unroll
            for (int p = 0; p < 4; p++) {
                float2 bv = *(const float2*)&Ks[kq][(tx << 1) + (p << 5)];
                b2[p] = f2u(bv.x, bv.y);
            }
#pragma unroll
            for (int i = 0; i < 8; i++) {
                float av = Qs[kq][(ty << 3) + i];
                a2[i] = f2u(av, av);
            }
#pragma unroll
            for (int i = 0; i < 8; i++)
#pragma unroll
                for (int p = 0; p < 4; p++) acc[i][p] = fma2(a2[i], b2[p], acc[i][p]);
        }
        __syncthreads();
    }

    // Epilogue: store S, per-row raw max/min, per-head sum/sumsq
    float psum = 0.f, psq = 0.f;
    float* Sb = g_S + ((size_t)bh << 20) + (size_t)l0 * 1024 + m0;
#pragma unroll
    for (int i = 0; i < 8; i++) {
        const int l = (ty << 3) + i;
        float vmax = -3.4e38f, vmin = 3.4e38f;
#pragma unroll
        for (int p = 0; p < 4; p++) {
            float2 v = u2f(acc[i][p]);
            psum += v.x + v.y;
            psq = fmaf(v.x, v.x, psq); psq = fmaf(v.y, v.y, psq);
            vmax = fmaxf(vmax, fmaxf(v.x, v.y));
            vmin = fminf(vmin, fminf(v.x, v.y));
            *(float2*)&Sb[(size_t)l * 1024 + (tx << 1) + (p << 5)] = v;
        }
#pragma unroll
        for (int off = 8; off > 0; off >>= 1) {          // reduce over 16 tx lanes
            vmax = fmaxf(vmax, __shfl_xor_sync(0xffffffffu, vmax, off));
            vmin = fminf(vmin, __shfl_xor_sync(0xffffffffu, vmin, off));
        }
        if (tx == 0) {
            atomicMax(&g_rmax[(bh << 10) + l0 + l], encf(vmax));
            atomicMin(&g_rmin[(bh << 10) + l0 + l], encf(vmin));
        }
    }
#pragma unroll
    for (int off = 16; off > 0; off >>= 1) {
        psum += __shfl_xor_sync(0xffffffffu, psum, off);
        psq  += __shfl_xor_sync(0xffffffffu, psq,  off);
    }
    __shared__ float r1[8], r2[8];
    if ((tid & 31) == 0) { r1[tid >> 5] = psum; r2[tid >> 5] = psq; }
    __syncthreads();
    if (tid == 0) {
        float s = 0.f, ss = 0.f;
#pragma unroll
        for (int i = 0; i < 8; i++) { s += r1[i]; ss += r2[i]; }
        atomicAdd(&g_hsum[bh & 7], s);
        atomicAdd(&g_hsq[bh & 7], ss);
    }
}

// ---------------- K2: per-head softmax scale --------------------------------
__global__ void k_statsA(const float* __restrict__ gsim) {
    int h = threadIdx.x;
    if (h < 8) {
        const float inv = 1.f / 8388608.f;               // N*L*M
        float mean = g_hsum[h] * inv;
        float var  = fmaf(-mean, mean, g_hsq[h] * inv);
        float a    = gsim[h] * rsqrtf(var + 1e-3f);
        g_aL2E[h]  = a * 1.4426950408889634f;            // to log2 domain
    }
}

// ---------------- K3: GEMM2 fused softmax -----------------------------------
// grid (16 l-tiles, 64 bh), 256 threads. Tile: 64 l x 64 c, M-chunks of 32.
// rv[c,l] = (sum_m e[l,m]*v[c,m]) / sum_m e[l,m]
__global__ void __launch_bounds__(256) k_gemm2(const float* __restrict__ v,
                                               float* __restrict__ out) {
    const int bh = blockIdx.y;
    const int h = bh & 7, bb = bh >> 3;
    const int l0 = blockIdx.x << 6;
    __shared__ float Es[32][66];   // [m-local][l], even pad -> aligned float2
    __shared__ float Vs[32][66];   // [m-local][c]
    __shared__ float zmax[64];
    __shared__ float rinv[64];
    const int tid = threadIdx.x;
    const int tx = tid & 15, ty = tid >> 4;
    const float aL2E = g_aL2E[h];

    if (tid < 64) {
        int idx = (bh << 10) + l0 + tid;
        float rmax = decf(g_rmax[idx]);
        float rmin = decf(g_rmin[idx]);
        zmax[tid] = (aL2E >= 0.f) ? aL2E * rmax : aL2E * rmin;
    }
    __syncthreads();

    const int lr = tid >> 3;            // 0..31  (rows lr and lr+32)
    const int ms = (tid & 7) << 2;      // m sub-offset
    const float zm0 = zmax[lr];
    const float zm1 = zmax[lr + 32];
    float rs0 = 0.f, rs1 = 0.f;

    ull acc[4][2];
#pragma unroll
    for (int c = 0; c < 4; c++)
#pragma unroll
        for (int p = 0; p < 2; p++) acc[c][p] = 0ull;

    const float* vb = v + (size_t)bh * 65536;
    const float* Sb = g_S + ((size_t)bh << 20) + (size_t)l0 * 1024;

    for (int m0 = 0; m0 < 1024; m0 += 32) {
        __syncthreads();
        // V tile 64x32 (transposed into smem)
#pragma unroll
        for (int j = 0; j < 2; j++) {
            int f = tid + (j << 8);
            int c = f >> 3, m4 = (f & 7) << 2;
            float4 vv = *(const float4*)&vb[(size_t)c * 1024 + m0 + m4];
            Vs[m4 + 0][c] = vv.x; Vs[m4 + 1][c] = vv.y;
            Vs[m4 + 2][c] = vv.z; Vs[m4 + 3][c] = vv.w;
        }
        // S tile 64x32 -> e = exp2(aL2E*s - zmax), rowsum alongside
        {
            float4 s0 = *(const float4*)&Sb[(size_t)lr * 1024 + m0 + ms];
            float4 s1 = *(const float4*)&Sb[(size_t)(lr + 32) * 1024 + m0 + ms];
            float e00 = exp2f(fmaf(aL2E, s0.x, -zm0));
            float e01 = exp2f(fmaf(aL2E, s0.y, -zm0));
            float e02 = exp2f(fmaf(aL2E, s0.z, -zm0));
            float e03 = exp2f(fmaf(aL2E, s0.w, -zm0));
            float e10 = exp2f(fmaf(aL2E, s1.x, -zm1));
            float e11 = exp2f(fmaf(aL2E, s1.y, -zm1));
            float e12 = exp2f(fmaf(aL2E, s1.z, -zm1));
            float e13 = exp2f(fmaf(aL2E, s1.w, -zm1));
            rs0 += (e00 + e01) + (e02 + e03);
            rs1 += (e10 + e11) + (e12 + e13);
            Es[ms + 0][lr] = e00; Es[ms + 1][lr] = e01;
            Es[ms + 2][lr] = e02; Es[ms + 3][lr] = e03;
            Es[ms + 0][lr + 32] = e10; Es[ms + 1][lr + 32] = e11;
            Es[ms + 2][lr + 32] = e12; Es[ms + 3][lr + 32] = e13;
        }
        __syncthreads();
#pragma unroll
        for (int mk = 0; mk < 32; mk++) {
            ull a2[4], b2[2];
#pragma unroll
            for (int p = 0; p < 2; p++) {
                float2 ev = *(const float2*)&Es[mk][(tx << 1) + (p << 5)];
                b2[p] = f2u(ev.x, ev.y);
            }
#pragma unroll
            for (int c = 0; c < 4; c++) {
                float av = Vs[mk][(ty << 2) + c];
                a2[c] = f2u(av, av);
            }
#pragma unroll
            for (int c = 0; c < 4; c++)
#pragma unroll
                for (int p = 0; p < 2; p++) acc[c][p] = fma2(a2[c], b2[p], acc[c][p]);
        }
    }

    // rowsum: 8 lanes per row -> reduce -> invert
#pragma unroll
    for (int off = 4; off > 0; off >>= 1) {
        rs0 += __shfl_xor_sync(0xffffffffu, rs0, off);
        rs1 += __shfl_xor_sync(0xffffffffu, rs1, off);
    }
    if ((tid & 7) == 0) { rinv[lr] = rs0; rinv[lr + 32] = rs1; }
    __syncthreads();
    if (tid < 64) rinv[tid] = 1.f / rinv[tid];
    __syncthreads();

    // Epilogue: divide, write rv into out, accumulate channel stats
#pragma unroll
    for (int c = 0; c < 4; c++) {
        const int ch = (h << 6) + (ty << 2) + c;       // channel = h*64 + c
        float csum = 0.f, csq = 0.f;
#pragma unroll
        for (int p = 0; p < 2; p++) {
            const int lc = (tx << 1) + (p << 5);
            float2 a = u2f(acc[c][p]);
            float2 rv;
            rv.x = a.x * rinv[lc];
            rv.y = a.y * rinv[lc + 1];
            csum += rv.x + rv.y;
            csq = fmaf(rv.x, rv.x, csq); csq = fmaf(rv.y, rv.y, csq);
            *(float2*)&out[((size_t)bb * 512 + ch) * 1024 + l0 + lc] = rv;
        }
#pragma unroll
        for (int off = 8; off > 0; off >>= 1) {
            csum += __shfl_xor_sync(0xffffffffu, csum, off);
            csq  += __shfl_xor_sync(0xffffffffu, csq,  off);
        }
        if (tx == 0) {
            atomicAdd(&g_vsum[ch], csum);
            atomicAdd(&g_vsq[ch],  csq);
        }
    }
}

// ---------------- K4: per-channel BN2 scale/bias ----------------------------
__global__ void k_statsB(const float* __restrict__ gval,
                         const float* __restrict__ bval) {
    int j = blockIdx.x * blockDim.x + threadIdx.x;
    if (j < 512) {
        const float inv = 1.f / 8192.f;                 // N*L
        float mean = g_vsum[j] * inv;
        float var  = fmaf(-mean, mean, g_vsq[j] * inv);
        float sc   = gval[j] * rsqrtf(var + 1e-3f);
        g_vscale[j] = sc;
        g_vbias[j]  = fmaf(-mean, sc, bval[j]);
    }
}

// ---------------- K5: BN2 apply + exact gelu (in place) ---------------------
__device__ __forceinline__ float gelu_exact(float x) {
    return 0.5f * x * (1.f + erff(x * 0.70710678118654752f));
}
__global__ void k_final(float* __restrict__ out) {
    int i4 = blockIdx.x * blockDim.x + threadIdx.x;     // 1048576 float4's
    int j = (i4 >> 8) & 511;                            // channel of element i4*4
    float sc = g_vscale[j], bi = g_vbias[j];
    float4 x = ((float4*)out)[i4];
    x.x = gelu_exact(fmaf(x.x, sc, bi));
    x.y = gelu_exact(fmaf(x.y, sc, bi));
    x.z = gelu_exact(fmaf(x.z, sc, bi));
    x.w = gelu_exact(fmaf(x.w, sc, bi));
    ((float4*)out)[i4] = x;
}

// ---------------- launch ----------------------------------------------------
extern "C" void kernel_launch(void* const* d_in, const int* in_sizes, int n_in,
                              void* d_out, int out_size) {
    (void)in_sizes; (void)n_in; (void)out_size;
    const float* q    = (const float*)d_in[0];
    const float* k    = (const float*)d_in[1];
    const float* v    = (const float*)d_in[2];
    const float* gsim = (const float*)d_in[3];
    // d_in[4] = beta_sim: provably no effect (softmax shift invariance)
    const float* gval = (const float*)d_in[5];
    const float* bval = (const float*)d_in[6];
    float* out = (float*)d_out;

    k_init  <<<256, 256>>>();
    k_gemm1 <<<dim3(8, 8, 64), 256>>>(q, k);
    k_statsA<<<1, 32>>>(gsim);
    k_gemm2 <<<dim3(16, 64), 256>>>(v, out);
    k_statsB<<<2, 256>>>(gval, bval);
    k_final <<<4096, 256>>>(out);
}

// round 2
// speedup vs baseline: 1.0017x; 1.0017x over previous
#include <cuda_runtime.h>
#include <cstdint>
#include <cstddef>

// ============================================================================
// AttentionOperation: S=QtK -> BN(head) -> softmax -> attn@V -> BN(chan) -> gelu
// N=8 H=8 D=C=64 L=M=1024.
// Strategy: BN1 shift cancels in softmax; only a_h = gamma*rstd matters.
//   K1: GEMM1 (fp32, packed f32x2 FMA) -> S scratch + per-head sum/sumsq +
//       per-row raw max/min (ordered-uint atomics).
//   K2: finalize per-head scale (in log2 domain).
//   K3: GEMM2 fused softmax: e=exp2(aL2E*s - zmax) on the fly, U=sum(e*v),
//       rowsum alongside, divide in epilogue, write rv into d_out (same layout),
//       accumulate per-channel sum/sumsq.
//   K4: finalize per-channel scale/bias.  K5: BN2 + exact gelu in place.
// ============================================================================

typedef unsigned long long ull;

__device__ __forceinline__ ull f2u(float x, float y) {
    ull u; asm("mov.b64 %0,{%1,%2};" : "=l"(u) : "f"(x), "f"(y)); return u;
}
__device__ __forceinline__ float2 u2f(ull u) {
    float2 f; asm("mov.b64 {%0,%1},%2;" : "=f"(f.x), "=f"(f.y) : "l"(u)); return f;
}
__device__ __forceinline__ ull fma2(ull a, ull b, ull c) {
    ull d; asm("fma.rn.f32x2 %0,%1,%2,%3;" : "=l"(d) : "l"(a), "l"(b), "l"(c)); return d;
}

// Monotonic float<->uint encoding for atomicMax/Min over signed floats
__device__ __forceinline__ unsigned encf(float f) {
    unsigned u = __float_as_uint(f);
    return (u & 0x80000000u) ? ~u : (u | 0x80000000u);
}
__device__ __forceinline__ float decf(unsigned e) {
    return __uint_as_float((e & 0x80000000u) ? (e & 0x7fffffffu) : ~e);
}

// ---------------- scratch (device globals; no runtime allocation) -----------
__device__ float    g_S[67108864];   // 256 MB: S[bh][l][m]
__device__ unsigned g_rmax[65536];   // per-row raw max (encoded)
__device__ unsigned g_rmin[65536];   // per-row raw min (encoded)
__device__ float    g_hsum[8], g_hsq[8];
__device__ float    g_aL2E[8];       // gamma*rstd*log2(e) per head
__device__ float    g_vsum[512], g_vsq[512];
__device__ float    g_vscale[512], g_vbias[512];

// ---------------- K0: init accumulators (graph-replay deterministic) --------
__global__ void k_init() {
    int i = blockIdx.x * blockDim.x + threadIdx.x;   // 65536 threads
    g_rmax[i] = 0u;
    g_rmin[i] = 0xFFFFFFFFu;
    if (i < 512) { g_vsum[i] = 0.f; g_vsq[i] = 0.f; }
    if (i < 8)   { g_hsum[i] = 0.f; g_hsq[i] = 0.f; }
}

// ---------------- K1: GEMM1  S[l,m] = sum_d q[d,l]*k[d,m] -------------------
// grid (8 m-tiles, 8 l-tiles, 64 bh), 256 threads, tile 128x128, K-chunk 16.
// Thread (tx,ty): l = ty*8+i (i<8), m = tx*2 + 32*p (+0/+1) (p<4) -> 8x8 outs.
__global__ void __launch_bounds__(256) k_gemm1(const float* __restrict__ q,
                                               const float* __restrict__ kk) {
    const int bh = blockIdx.z;
    const int l0 = blockIdx.y << 7;
    const int m0 = blockIdx.x << 7;
    __shared__ float Qs[16][128];
    __shared__ float Ks[16][128];
    const int tid = threadIdx.x;
    const int tx = tid & 15, ty = tid >> 4;
    const float* qb = q  + (size_t)bh * 65536 + l0;
    const float* kb = kk + (size_t)bh * 65536 + m0;

    ull acc[8][4];
#pragma unroll
    for (int i = 0; i < 8; i++)
#pragma unroll
        for (int p = 0; p < 4; p++) acc[i][p] = 0ull;

    for (int d0 = 0; d0 < 64; d0 += 16) {
#pragma unroll
        for (int j = 0; j < 2; j++) {
            int f = tid + (j << 8);
            int dr = f >> 5, c4 = (f & 31) << 2;
            *(float4*)&Qs[dr][c4] = *(const float4*)&qb[(size_t)(d0 + dr) * 1024 + c4];
            *(float4*)&Ks[dr][c4] = *(const float4*)&kb[(size_t)(d0 + dr) * 1024 + c4];
        }
        __syncthreads();
#pragma unroll
        for (int kq = 0; kq < 16; kq++) {
            ull a2[8], b2[4];
#pragma unroll
            for (int p = 0; p < 4; p++) {
                float2 bv = *(const float2*)&Ks[kq][(tx << 1) + (p << 5)];
                b2[p] = f2u(bv.x, bv.y);
            }
#pragma unroll
            for (int i = 0; i < 8; i++) {
                float av = Qs[kq][(ty << 3) + i];
                a2[i] = f2u(av, av);
            }
#pragma unroll
            for (int i = 0; i < 8; i++)
#pragma unroll
                for (int p = 0; p < 4; p++) acc[i][p] = fma2(a2[i], b2[p], acc[i][p]);
        }
        __syncthreads();
    }

    // Epilogue: store S, per-row raw max/min, per-head sum/sumsq
    float psum = 0.f, psq = 0.f;
    float* Sb = g_S + ((size_t)bh << 20) + (size_t)l0 * 1024 + m0;
#pragma unroll
    for (int i = 0; i < 8; i++) {
        const int l = (ty << 3) + i;
        float vmax = -3.4e38f, vmin = 3.4e38f;
#pragma unroll
        for (int p = 0; p < 4; p++) {
            float2 v = u2f(acc[i][p]);
            psum += v.x + v.y;
            psq = fmaf(v.x, v.x, psq); psq = fmaf(v.y, v.y, psq);
            vmax = fmaxf(vmax, fmaxf(v.x, v.y));
            vmin = fminf(vmin, fminf(v.x, v.y));
            *(float2*)&Sb[(size_t)l * 1024 + (tx << 1) + (p << 5)] = v;
        }
#pragma unroll
        for (int off = 8; off > 0; off >>= 1) {          // reduce over 16 tx lanes
            vmax = fmaxf(vmax, __shfl_xor_sync(0xffffffffu, vmax, off));
            vmin = fminf(vmin, __shfl_xor_sync(0xffffffffu, vmin, off));
        }
        if (tx == 0) {
            atomicMax(&g_rmax[(bh << 10) + l0 + l], encf(vmax));
            atomicMin(&g_rmin[(bh << 10) + l0 + l], encf(vmin));
        }
    }
#pragma unroll
    for (int off = 16; off > 0; off >>= 1) {
        psum += __shfl_xor_sync(0xffffffffu, psum, off);
        psq  += __shfl_xor_sync(0xffffffffu, psq,  off);
    }
    __shared__ float r1[8], r2[8];
    if ((tid & 31) == 0) { r1[tid >> 5] = psum; r2[tid >> 5] = psq; }
    __syncthreads();
    if (tid == 0) {
        float s = 0.f, ss = 0.f;
#pragma unroll
        for (int i = 0; i < 8; i++) { s += r1[i]; ss += r2[i]; }
        atomicAdd(&g_hsum[bh & 7], s);
        atomicAdd(&g_hsq[bh & 7], ss);
    }
}

// ---------------- K2: per-head softmax scale --------------------------------
__global__ void k_statsA(const float* __restrict__ gsim) {
    int h = threadIdx.x;
    if (h < 8) {
        const float inv = 1.f / 8388608.f;               // N*L*M
        float mean = g_hsum[h] * inv;
        float var  = fmaf(-mean, mean, g_hsq[h] * inv);
        float a    = gsim[h] * rsqrtf(var + 1e-3f);
        g_aL2E[h]  = a * 1.4426950408889634f;            // to log2 domain
    }
}

// ---------------- K3: GEMM2 fused softmax -----------------------------------
// grid (16 l-tiles, 64 bh), 256 threads. Tile: 64 l x 64 c, M-chunks of 32.
// rv[c,l] = (sum_m e[l,m]*v[c,m]) / sum_m e[l,m]
__global__ void __launch_bounds__(256) k_gemm2(const float* __restrict__ v,
                                               float* __restrict__ out) {
    const int bh = blockIdx.y;
    const int h = bh & 7, bb = bh >> 3;
    const int l0 = blockIdx.x << 6;
    __shared__ float Es[32][66];   // [m-local][l], even pad -> aligned float2
    __shared__ float Vs[32][66];   // [m-local][c]
    __shared__ float zmax[64];
    __shared__ float rinv[64];
    const int tid = threadIdx.x;
    const int tx = tid & 15, ty = tid >> 4;
    const float aL2E = g_aL2E[h];

    if (tid < 64) {
        int idx = (bh << 10) + l0 + tid;
        float rmax = decf(g_rmax[idx]);
        float rmin = decf(g_rmin[idx]);
        zmax[tid] = (aL2E >= 0.f) ? aL2E * rmax : aL2E * rmin;
    }
    __syncthreads();

    const int lr = tid >> 3;            // 0..31  (rows lr and lr+32)
    const int ms = (tid & 7) << 2;      // m sub-offset
    const float zm0 = zmax[lr];
    const float zm1 = zmax[lr + 32];
    float rs0 = 0.f, rs1 = 0.f;

    ull acc[4][2];
#pragma unroll
    for (int c = 0; c < 4; c++)
#pragma unroll
        for (int p = 0; p < 2; p++) acc[c][p] = 0ull;

    const float* vb = v + (size_t)bh * 65536;
    const float* Sb = g_S + ((size_t)bh << 20) + (size_t)l0 * 1024;

    for (int m0 = 0; m0 < 1024; m0 += 32) {
        __syncthreads();
        // V tile 64x32 (transposed into smem)
#pragma unroll
        for (int j = 0; j < 2; j++) {
            int f = tid + (j << 8);
            int c = f >> 3, m4 = (f & 7) << 2;
            float4 vv = *(const float4*)&vb[(size_t)c * 1024 + m0 + m4];
            Vs[m4 + 0][c] = vv.x; Vs[m4 + 1][c] = vv.y;
            Vs[m4 + 2][c] = vv.z; Vs[m4 + 3][c] = vv.w;
        }
        // S tile 64x32 -> e = exp2(aL2E*s - zmax), rowsum alongside
        {
            float4 s0 = *(const float4*)&Sb[(size_t)lr * 1024 + m0 + ms];
            float4 s1 = *(const float4*)&Sb[(size_t)(lr + 32) * 1024 + m0 + ms];
            float e00 = exp2f(fmaf(aL2E, s0.x, -zm0));
            float e01 = exp2f(fmaf(aL2E, s0.y, -zm0));
            float e02 = exp2f(fmaf(aL2E, s0.z, -zm0));
            float e03 = exp2f(fmaf(aL2E, s0.w, -zm0));
            float e10 = exp2f(fmaf(aL2E, s1.x, -zm1));
            float e11 = exp2f(fmaf(aL2E, s1.y, -zm1));
            float e12 = exp2f(fmaf(aL2E, s1.z, -zm1));
            float e13 = exp2f(fmaf(aL2E, s1.w, -zm1));
            rs0 += (e00 + e01) + (e02 + e03);
            rs1 += (e10 + e11) + (e12 + e13);
            Es[ms + 0][lr] = e00; Es[ms + 1][lr] = e01;
            Es[ms + 2][lr] = e02; Es[ms + 3][lr] = e03;
            Es[ms + 0][lr + 32] = e10; Es[ms + 1][lr + 32] = e11;
            Es[ms + 2][lr + 32] = e12; Es[ms + 3][lr + 32] = e13;
        }
        __syncthreads();
#pragma unroll
        for (int mk = 0; mk < 32; mk++) {
            ull a2[4], b2[2];
#pragma unroll
            for (int p = 0; p < 2; p++) {
                float2 ev = *(const float2*)&Es[mk][(tx << 1) + (p << 5)];
                b2[p] = f2u(ev.x, ev.y);
            }
#pragma unroll
            for (int c = 0; c < 4; c++) {
                float av = Vs[mk][(ty << 2) + c];
                a2[c] = f2u(av, av);
            }
#pragma unroll
            for (int c = 0; c < 4; c++)
#pragma unroll
                for (int p = 0; p < 2; p++) acc[c][p] = fma2(a2[c], b2[p], acc[c][p]);
        }
    }

    // rowsum: 8 lanes per row -> reduce -> invert
#pragma unroll
    for (int off = 4; off > 0; off >>= 1) {
        rs0 += __shfl_xor_sync(0xffffffffu, rs0, off);
        rs1 += __shfl_xor_sync(0xffffffffu, rs1, off);
    }
    if ((tid & 7) == 0) { rinv[lr] = rs0; rinv[lr + 32] = rs1; }
    __syncthreads();
    if (tid < 64) rinv[tid] = 1.f / rinv[tid];
    __syncthreads();

    // Epilogue: divide, write rv into out, accumulate channel stats
#pragma unroll
    for (int c = 0; c < 4; c++) {
        const int ch = (h << 6) + (ty << 2) + c;       // channel = h*64 + c
        float csum = 0.f, csq = 0.f;
#pragma unroll
        for (int p = 0; p < 2; p++) {
            const int lc = (tx << 1) + (p << 5);
            float2 a = u2f(acc[c][p]);
            float2 rv;
            rv.x = a.x * rinv[lc];
            rv.y = a.y * rinv[lc + 1];
            csum += rv.x + rv.y;
            csq = fmaf(rv.x, rv.x, csq); csq = fmaf(rv.y, rv.y, csq);
            *(float2*)&out[((size_t)bb * 512 + ch) * 1024 + l0 + lc] = rv;
        }
#pragma unroll
        for (int off = 8; off > 0; off >>= 1) {
            csum += __shfl_xor_sync(0xffffffffu, csum, off);
            csq  += __shfl_xor_sync(0xffffffffu, csq,  off);
        }
        if (tx == 0) {
            atomicAdd(&g_vsum[ch], csum);
            atomicAdd(&g_vsq[ch],  csq);
        }
    }
}

// ---------------- K4: per-channel BN2 scale/bias ----------------------------
__global__ void k_statsB(const float* __restrict__ gval,
                         const float* __restrict__ bval) {
    int j = blockIdx.x * blockDim.x + threadIdx.x;
    if (j < 512) {
        const float inv = 1.f / 8192.f;                 // N*L
        float mean = g_vsum[j] * inv;
        float var  = fmaf(-mean, mean, g_vsq[j] * inv);
        float sc   = gval[j] * rsqrtf(var + 1e-3f);
        g_vscale[j] = sc;
        g_vbias[j]  = fmaf(-mean, sc, bval[j]);
    }
}

// ---------------- K5: BN2 apply + exact gelu (in place) ---------------------
__device__ __forceinline__ float gelu_exact(float x) {
    return 0.5f * x * (1.f + erff(x * 0.70710678118654752f));
}
__global__ void k_final(float* __restrict__ out) {
    int i4 = blockIdx.x * blockDim.x + threadIdx.x;     // 1048576 float4's
    int j = (i4 >> 8) & 511;                            // channel of element i4*4
    float sc = g_vscale[j], bi = g_vbias[j];
    float4 x = ((float4*)out)[i4];
    x.x = gelu_exact(fmaf(x.x, sc, bi));
    x.y = gelu_exact(fmaf(x.y, sc, bi));
    x.z = gelu_exact(fmaf(x.z, sc, bi));
    x.w = gelu_exact(fmaf(x.w, sc, bi));
    ((float4*)out)[i4] = x;
}

// ---------------- launch ----------------------------------------------------
extern "C" void kernel_launch(void* const* d_in, const int* in_sizes, int n_in,
                              void* d_out, int out_size) {
    (void)in_sizes; (void)n_in; (void)out_size;
    const float* q    = (const float*)d_in[0];
    const float* k    = (const float*)d_in[1];
    const float* v    = (const float*)d_in[2];
    const float* gsim = (const float*)d_in[3];
    // d_in[4] = beta_sim: provably no effect (softmax shift invariance)
    const float* gval = (const float*)d_in[5];
    const float* bval = (const float*)d_in[6];
    float* out = (float*)d_out;

    k_init  <<<256, 256>>>();
    k_gemm1 <<<dim3(8, 8, 64), 256>>>(q, k);
    k_statsA<<<1, 32>>>(gsim);
    k_gemm2 <<<dim3(16, 64), 256>>>(v, out);
    k_statsB<<<2, 256>>>(gval, bval);
    k_final <<<4096, 256>>>(out);
}